// round 5
// baseline (speedup 1.0000x reference)
#include <cuda_runtime.h>
#include <cstdint>

typedef unsigned long long ull;

// ---- packed f32x2 helpers: per-lane IEEE fp32 semantics (ptxas won't auto-fuse) ----
__device__ __forceinline__ ull fma2(ull a, ull b, ull c) {
    ull d;
    asm("fma.rn.f32x2 %0, %1, %2, %3;" : "=l"(d) : "l"(a), "l"(b), "l"(c));
    return d;
}
__device__ __forceinline__ ull add2(ull a, ull b) {
    ull d;
    asm("add.rn.f32x2 %0, %1, %2;" : "=l"(d) : "l"(a), "l"(b));
    return d;
}
__device__ __forceinline__ float ulo(ull v) { return __uint_as_float((unsigned)v); }
__device__ __forceinline__ float uhi(ull v) { return __uint_as_float((unsigned)(v >> 32)); }
// volatile: must materialize at use site; hoisting all 64 dups would blow registers.
__device__ __forceinline__ ull dup2v(float x) {
    ull d;
    asm volatile("mov.b64 %0, {%1, %1};" : "=l"(d) : "f"(x));
    return d;
}
__device__ __forceinline__ ull dup2(float x) {
    unsigned u = __float_as_uint(x);
    return ((ull)u << 32) | (ull)u;
}

static constexpr int D       = 64;
static constexpr int HW      = 4096;
static constexpr int K       = 512;
static constexpr int N_VEC   = 131072;
static constexpr int N_ELEMS = N_VEC * D;         // 8388608
static constexpr int LOSS_OFF = N_ELEMS;
static constexpr int IDX_OFF  = N_ELEMS + 1;
static constexpr int THREADS  = 256;
static constexpr int NCTA     = 148;              // one CTA per SM
static constexpr int NPAIR    = N_VEC / 2;        // 65536 vector-pairs
static constexpr int BASEP    = NCTA * THREADS;   // 37888 pairs in pass 0
// remaining 27648 pairs split contiguously per CTA: start(c) = (c*6912)/37
static constexpr int SMEM_BYTES = (D * K + K) * 4;

__device__ double   g_loss = 0.0;
__device__ unsigned g_done = 0u;

// 148 CTAs x 256 threads, 2 vectors (one adjacent pixel-pair) per thread-iteration,
// 1-2 iterations per thread (balanced within every CTA -> no wave tail).
// EXACT-INVARIANT (verified rel_err==0.0 twice, do not change):
//   d_k  = fl32( fl32(S + E_k) + (-2)*dot_k )
//   dot_k = strict sequential fp32 FMA chain over d=0..63
//   S     = 4-lane stride-4 sums combined (l0+l2)+(l1+l3)
//   argmin: strict '<', first-min tie-break (ascending k)
//   out   = fl(x + fl(q - x))
__global__ __launch_bounds__(THREADS, 1)
void k_main(const float* __restrict__ in, const float* __restrict__ emb,
            float* __restrict__ out, int write_extras) {
    extern __shared__ float s[];
    float* sT = s;            // [d][k] transposed codebook
    float* sE = s + D * K;    // [K] code squared norms
    __shared__ double red[8];

    const int tid = threadIdx.x;
    const int c   = blockIdx.x;

    // ---- stage codebook TRANSPOSED ----
#pragma unroll
    for (int i = 0; i < 128; i++) {
        int lin = i * THREADS + tid;      // 0..32767
        int k = lin & 511;
        int d = lin >> 9;
        sT[d * K + k] = emb[k * D + d];
    }
    __syncthreads();

    // ---- E_k = sum(emb*emb, axis=1), XLA 4-lane pattern; 2 codes per thread ----
#pragma unroll
    for (int j = 0; j < 2; j++) {
        const int k = tid * 2 + j;
        const float* r = emb + k * D;
        float l0 = 0.f, l1 = 0.f, l2 = 0.f, l3 = 0.f;
#pragma unroll
        for (int i = 0; i < 16; i++) {
            l0 = __fadd_rn(l0, __fmul_rn(r[4 * i + 0], r[4 * i + 0]));
            l1 = __fadd_rn(l1, __fmul_rn(r[4 * i + 1], r[4 * i + 1]));
            l2 = __fadd_rn(l2, __fmul_rn(r[4 * i + 2], r[4 * i + 2]));
            l3 = __fadd_rn(l3, __fmul_rn(r[4 * i + 3], r[4 * i + 3]));
        }
        sE[k] = __fadd_rn(__fadd_rn(l0, l2), __fadd_rn(l1, l3));
    }
    __syncthreads();

    const ull NEG2 = dup2(-2.0f);
    double lsum = 0.0;

    for (int it = 0; it < 2; it++) {
        int pr;
        bool active;
        if (it == 0) {
            pr = c * THREADS + tid;                 // < BASEP always
            active = true;
        } else {
            int s0 = (c * 6912) / 37;
            int s1 = ((c + 1) * 6912) / 37;
            pr = BASEP + s0 + tid;
            active = tid < (s1 - s0);               // 186-187 threads per CTA
        }
        if (!active) continue;

        const int v = pr * 2;                       // vecA = v, vecB = v+1 (adjacent pixels)
        const int b = v >> 12;
        const int p = v & 4095;                     // even -> float2 aligned
        const float2* xg = (const float2*)(in + b * (D * HW) + p);

        // ---- load both vectors (float2 coalesced per d-plane) + S (XLA 4-lane) ----
        float xa[64], xb[64];
        float la0 = 0.f, la1 = 0.f, la2 = 0.f, la3 = 0.f;
        float lb0 = 0.f, lb1 = 0.f, lb2 = 0.f, lb3 = 0.f;
#pragma unroll
        for (int d = 0; d < 64; d += 4) {
            float2 q0 = xg[(d + 0) * (HW / 2)];
            float2 q1 = xg[(d + 1) * (HW / 2)];
            float2 q2 = xg[(d + 2) * (HW / 2)];
            float2 q3 = xg[(d + 3) * (HW / 2)];
            xa[d + 0] = q0.x; xb[d + 0] = q0.y;
            xa[d + 1] = q1.x; xb[d + 1] = q1.y;
            xa[d + 2] = q2.x; xb[d + 2] = q2.y;
            xa[d + 3] = q3.x; xb[d + 3] = q3.y;
            la0 = __fadd_rn(la0, __fmul_rn(q0.x, q0.x));
            la1 = __fadd_rn(la1, __fmul_rn(q1.x, q1.x));
            la2 = __fadd_rn(la2, __fmul_rn(q2.x, q2.x));
            la3 = __fadd_rn(la3, __fmul_rn(q3.x, q3.x));
            lb0 = __fadd_rn(lb0, __fmul_rn(q0.y, q0.y));
            lb1 = __fadd_rn(lb1, __fmul_rn(q1.y, q1.y));
            lb2 = __fadd_rn(lb2, __fmul_rn(q2.y, q2.y));
            lb3 = __fadd_rn(lb3, __fmul_rn(q3.y, q3.y));
        }
        const float SA = __fadd_rn(__fadd_rn(la0, la2), __fadd_rn(la1, la3));
        const float SB = __fadd_rn(__fadd_rn(lb0, lb2), __fadd_rn(lb1, lb3));
        const ull SA2 = dup2(SA);
        const ull SB2 = dup2(SB);

        // ---- argmin, k-tiles of 8; each e-load feeds BOTH vectors ----
        float bestA = 3.4e38f, bestB = 3.4e38f;
        int iA = 0, iB = 0;
        for (int k = 0; k < K; k += 8) {
            ull A0 = 0ull, A1 = 0ull, A2 = 0ull, A3 = 0ull;
            ull B0 = 0ull, B1 = 0ull, B2 = 0ull, B3 = 0ull;
#pragma unroll
            for (int d = 0; d < 64; d++) {
                const float* row = sT + d * K + k;       // broadcast LDS.128 x2
                ulonglong2 e01 = *(const ulonglong2*)(row);
                ulonglong2 e23 = *(const ulonglong2*)(row + 4);
                ull xva = dup2v(xa[d]);
                ull xvb = dup2v(xb[d]);
                A0 = fma2(xva, e01.x, A0);
                A1 = fma2(xva, e01.y, A1);
                A2 = fma2(xva, e23.x, A2);
                A3 = fma2(xva, e23.y, A3);
                B0 = fma2(xvb, e01.x, B0);
                B1 = fma2(xvb, e01.y, B1);
                B2 = fma2(xvb, e23.x, B2);
                B3 = fma2(xvb, e23.y, B3);
            }
            ull Aacc[4] = { A0, A1, A2, A3 };
            ull Bacc[4] = { B0, B1, B2, B3 };
            const ull* ep = (const ull*)(sE + k);        // E pairs, broadcast LDS.64
#pragma unroll
            for (int j = 0; j < 4; j++) {
                ull t1a = add2(SA2, ep[j]);              // fl(S + E)
                ull da  = fma2(Aacc[j], NEG2, t1a);      // fl(t1 - 2*dot)
                float a0 = ulo(da), a1 = uhi(da);
                if (a0 < bestA) { bestA = a0; iA = k + 2 * j; }
                if (a1 < bestA) { bestA = a1; iA = k + 2 * j + 1; }
                ull t1b = add2(SB2, ep[j]);
                ull db  = fma2(Bacc[j], NEG2, t1b);
                float b0 = ulo(db), b1 = uhi(db);
                if (b0 < bestB) { bestB = b0; iB = k + 2 * j; }
                if (b1 < bestB) { bestB = b1; iB = k + 2 * j + 1; }
            }
        }

        // ---- gather codes, straight-through output (float2), loss ----
        float2* og = (float2*)(out + b * (D * HW) + p);
#pragma unroll
        for (int d = 0; d < 64; d++) {
            float qa = sT[d * K + iA];
            float qb = sT[d * K + iB];
            float ta = __fsub_rn(qa, xa[d]);             // fl(q - x)
            float tb = __fsub_rn(qb, xb[d]);
            float2 o;
            o.x = __fadd_rn(xa[d], ta);                  // fl(x + (q - x))
            o.y = __fadd_rn(xb[d], tb);
            og[d * (HW / 2)] = o;
            lsum += (double)ta * (double)ta + (double)tb * (double)tb;
        }

        if (write_extras) {
            out[IDX_OFF + v]     = (float)iA;
            out[IDX_OFF + v + 1] = (float)iB;
        }
    }

    // ---- loss block-reduce -> atomic; last CTA finalizes & resets globals ----
#pragma unroll
    for (int o = 16; o; o >>= 1) lsum += __shfl_down_sync(0xffffffffu, lsum, o);
    if ((tid & 31) == 0) red[tid >> 5] = lsum;
    __syncthreads();
    if (tid == 0) {
        double t = 0.0;
#pragma unroll
        for (int w = 0; w < 8; w++) t += red[w];
        atomicAdd(&g_loss, t);
        __threadfence();
        unsigned done = atomicAdd(&g_done, 1u);
        if (done == (unsigned)(gridDim.x - 1)) {
            if (write_extras)
                out[LOSS_OFF] = (float)(0.25 * g_loss / (double)N_ELEMS);
            g_loss = 0.0;          // reset for next (graph-replayed) launch
            g_done = 0u;
        }
    }
}

extern "C" void kernel_launch(void* const* d_in, const int* in_sizes, int n_in,
                              void* d_out, int out_size) {
    const float* in  = (const float*)d_in[0];
    const float* emb = (const float*)d_in[1];
    if (n_in >= 2 && in_sizes[0] == K * D && in_sizes[1] == N_ELEMS) {
        const float* t = in; in = emb; emb = t;
    }
    float* out = (float*)d_out;

    cudaFuncSetAttribute(k_main, cudaFuncAttributeMaxDynamicSharedMemorySize, SMEM_BYTES);

    const int extras = (out_size > N_ELEMS) ? 1 : 0;

    k_main<<<NCTA, THREADS, SMEM_BYTES>>>(in, emb, out, extras);
}

// round 6
// speedup vs baseline: 1.6635x; 1.6635x over previous
#include <cuda_runtime.h>
#include <cstdint>

typedef unsigned long long ull;

// ---- packed f32x2 helpers: per-lane IEEE fp32 semantics ----
__device__ __forceinline__ ull fma2(ull a, ull b, ull c) {
    ull d;
    asm("fma.rn.f32x2 %0, %1, %2, %3;" : "=l"(d) : "l"(a), "l"(b), "l"(c));
    return d;
}
__device__ __forceinline__ ull add2(ull a, ull b) {
    ull d;
    asm("add.rn.f32x2 %0, %1, %2;" : "=l"(d) : "l"(a), "l"(b));
    return d;
}
__device__ __forceinline__ float ulo(ull v) { return __uint_as_float((unsigned)v); }
__device__ __forceinline__ float uhi(ull v) { return __uint_as_float((unsigned)(v >> 32)); }
// non-volatile asm dup: can't be hoisted (data-dependent), scheduler stays free
__device__ __forceinline__ ull dup2a(float x) {
    ull d;
    asm("mov.b64 %0, {%1, %1};" : "=l"(d) : "f"(x));
    return d;
}
__device__ __forceinline__ ull dup2(float x) {
    unsigned u = __float_as_uint(x);
    return ((ull)u << 32) | (ull)u;
}

static constexpr int D       = 64;
static constexpr int HW      = 4096;
static constexpr int K       = 512;
static constexpr int N_VEC   = 131072;
static constexpr int N_ELEMS = N_VEC * D;         // 8388608
static constexpr int LOSS_OFF = N_ELEMS;
static constexpr int IDX_OFF  = N_ELEMS + 1;
static constexpr int THREADS  = 256;
static constexpr int NCTA     = 148;
static constexpr int VTILE    = 128;              // vectors per CTA-tile
static constexpr int NTILE    = N_VEC / VTILE;    // 1024

// smem layout (floats)
static constexpr int OFF_T  = 0;                  // sT  [64][512] codebook transposed
static constexpr int OFF_E  = 32768;              // sE  [512]
static constexpr int OFF_X  = 33280;              // sX  [64][128]
static constexpr int OFF_S  = 41472;              // sS  [128]
static constexpr int OFF_CD = 41600;              // sCd [128][16] candidate dists
static constexpr int OFF_CI = 43648;              // sCi [128][16] candidate idx (as int)
static constexpr int SMEM_FLOATS = 45696;
static constexpr int SMEM_BYTES  = SMEM_FLOATS * 4;   // 182784

__device__ double   g_loss = 0.0;
__device__ unsigned g_done = 0u;

// Persistent: 148 CTAs x 256 threads; each CTA processes 128-vector tiles vs all 512 codes.
// Thread tile: 8 vectors (4 f32x2 pairs) x 16 codes -> 64 fma2 per d-iter, x/e from smem.
// EXACT-INVARIANT (verified rel_err==0.0 three times, do not change):
//   d_k  = fl32( fl32(S + E_k) + (-2)*dot_k )
//   dot_k = strict sequential fp32 FMA chain over d=0..63
//   S     = 4-lane stride-4 sums combined (l0+l2)+(l1+l3)
//   argmin: strict '<', first-min in ascending k (in-thread asc k; cross-thread asc tk)
//   out   = fl(x + fl(q - x))
__global__ __launch_bounds__(THREADS, 1)
void k_main(const float* __restrict__ in, const float* __restrict__ emb,
            float* __restrict__ out, int write_extras) {
    extern __shared__ float s[];
    float* sT = s + OFF_T;
    float* sE = s + OFF_E;
    float* sX = s + OFF_X;
    float* sS = s + OFF_S;
    float* sCd = s + OFF_CD;
    int*   sCi = (int*)(s + OFF_CI);
    __shared__ double red[8];

    const int tid = threadIdx.x;
    const int tv  = tid & 15;    // vector-group 0..15 (8 vectors each)
    const int tk  = tid >> 4;    // code-group  0..15 (32 codes each)

    // ---- stage codebook TRANSPOSED ----
#pragma unroll
    for (int i = 0; i < 128; i++) {
        int lin = i * THREADS + tid;      // 0..32767
        int k = lin & 511;
        int d = lin >> 9;
        sT[d * K + k] = emb[k * D + d];
    }

    // ---- E_k: XLA 4-lane pattern, 2 codes/thread ----
#pragma unroll
    for (int j = 0; j < 2; j++) {
        const int k = tid * 2 + j;
        const float* r = emb + k * D;
        float l0 = 0.f, l1 = 0.f, l2 = 0.f, l3 = 0.f;
#pragma unroll
        for (int i = 0; i < 16; i++) {
            l0 = __fadd_rn(l0, __fmul_rn(r[4 * i + 0], r[4 * i + 0]));
            l1 = __fadd_rn(l1, __fmul_rn(r[4 * i + 1], r[4 * i + 1]));
            l2 = __fadd_rn(l2, __fmul_rn(r[4 * i + 2], r[4 * i + 2]));
            l3 = __fadd_rn(l3, __fmul_rn(r[4 * i + 3], r[4 * i + 3]));
        }
        sE[k] = __fadd_rn(__fadd_rn(l0, l2), __fadd_rn(l1, l3));
    }
    __syncthreads();

    const ull NEG2 = dup2(-2.0f);
    double lsum = 0.0;

    for (int tile = blockIdx.x; tile < NTILE; tile += NCTA) {
        const int v0 = tile * VTILE;
        const int b  = v0 >> 12;
        const int p  = v0 & 4095;
        const float* xg = in + b * (D * HW) + p;

        // ---- stage x tile [d][128] (coalesced) ----
#pragma unroll
        for (int i = 0; i < 32; i++) {
            int lin = i * THREADS + tid;       // 0..8191
            int d   = lin >> 7;
            int vv  = lin & 127;
            sX[lin] = xg[d * HW + vv];
        }
        __syncthreads();

        // ---- S per vector (threads 0..127), exact 4-lane pattern ----
        if (tid < VTILE) {
            float l0 = 0.f, l1 = 0.f, l2 = 0.f, l3 = 0.f;
#pragma unroll
            for (int d = 0; d < 64; d += 4) {
                float x0 = sX[(d + 0) * VTILE + tid];
                float x1 = sX[(d + 1) * VTILE + tid];
                float x2 = sX[(d + 2) * VTILE + tid];
                float x3 = sX[(d + 3) * VTILE + tid];
                l0 = __fadd_rn(l0, __fmul_rn(x0, x0));
                l1 = __fadd_rn(l1, __fmul_rn(x1, x1));
                l2 = __fadd_rn(l2, __fmul_rn(x2, x2));
                l3 = __fadd_rn(l3, __fmul_rn(x3, x3));
            }
            sS[tid] = __fadd_rn(__fadd_rn(l0, l2), __fadd_rn(l1, l3));
        }
        __syncthreads();

        // ---- mainloop: 8 vec x 32 codes per thread (2 k-tiles of 16) ----
        float bestD[8];
        int   bestI[8];
#pragma unroll
        for (int j = 0; j < 8; j++) { bestD[j] = 3.4e38f; bestI[j] = 0; }

        const ull* sSp = (const ull*)(sS + tv * 8);   // 4 S-pairs for this vec-group
        ull SAB[4];
#pragma unroll
        for (int vp = 0; vp < 4; vp++) SAB[vp] = sSp[vp];

        for (int kt = 0; kt < 2; kt++) {
            const int kb = tk * 32 + kt * 16;
            ull acc[64];
#pragma unroll
            for (int i = 0; i < 64; i++) acc[i] = 0ull;

#pragma unroll 4
            for (int d = 0; d < 64; d++) {
                const float* xr = sX + d * VTILE + tv * 8;
                ulonglong2 x01 = *(const ulonglong2*)(xr);       // vec pairs (0,1),(2,3)
                ulonglong2 x23 = *(const ulonglong2*)(xr + 4);   // (4,5),(6,7)
                const float4* er = (const float4*)(sT + d * K + kb);
                float4 e0 = er[0], e1 = er[1], e2 = er[2], e3 = er[3];
                float ev[16] = { e0.x, e0.y, e0.z, e0.w, e1.x, e1.y, e1.z, e1.w,
                                 e2.x, e2.y, e2.z, e2.w, e3.x, e3.y, e3.z, e3.w };
#pragma unroll
                for (int cc = 0; cc < 16; cc++) {
                    ull ed = dup2a(ev[cc]);
                    acc[0 * 16 + cc] = fma2(x01.x, ed, acc[0 * 16 + cc]);
                    acc[1 * 16 + cc] = fma2(x01.y, ed, acc[1 * 16 + cc]);
                    acc[2 * 16 + cc] = fma2(x23.x, ed, acc[2 * 16 + cc]);
                    acc[3 * 16 + cc] = fma2(x23.y, ed, acc[3 * 16 + cc]);
                }
            }

            // epilogue: distances + running argmin (ascending k)
#pragma unroll
            for (int cc = 0; cc < 16; cc++) {
                const int kk = kb + cc;
                ull Ec = dup2a(sE[kk]);
#pragma unroll
                for (int vp = 0; vp < 4; vp++) {
                    ull t1 = add2(SAB[vp], Ec);                    // fl(S + E)
                    ull dd = fma2(acc[vp * 16 + cc], NEG2, t1);    // fl(t1 - 2*dot)
                    float d0 = ulo(dd), d1 = uhi(dd);
                    if (d0 < bestD[2 * vp])     { bestD[2 * vp] = d0;     bestI[2 * vp] = kk; }
                    if (d1 < bestD[2 * vp + 1]) { bestD[2 * vp + 1] = d1; bestI[2 * vp + 1] = kk; }
                }
            }
        }

        // ---- publish candidates [vec][tk] ----
#pragma unroll
        for (int j = 0; j < 8; j++) {
            const int vv = tv * 8 + j;
            sCd[vv * 16 + tk] = bestD[j];
            sCi[vv * 16 + tk] = bestI[j];
        }
        __syncthreads();

        // ---- final reduce (ascending tk = ascending k) + gather + store + loss ----
        if (tid < VTILE) {
            float best = 3.4e38f;
            int bi = 0;
#pragma unroll
            for (int t2 = 0; t2 < 16; t2++) {
                float dd = sCd[tid * 16 + t2];
                if (dd < best) { best = dd; bi = sCi[tid * 16 + t2]; }
            }
            float* og = out + b * (D * HW) + p + tid;
#pragma unroll
            for (int d = 0; d < 64; d++) {
                float q  = sT[d * K + bi];
                float xv = sX[d * VTILE + tid];
                float t  = __fsub_rn(q, xv);       // fl(q - x)
                og[d * HW] = __fadd_rn(xv, t);     // fl(x + (q - x))
                lsum += (double)t * (double)t;
            }
            if (write_extras) out[IDX_OFF + v0 + tid] = (float)bi;
        }
        __syncthreads();   // protect sX/sCd before next tile
    }

    // ---- loss block-reduce -> atomic; last CTA finalizes & resets globals ----
#pragma unroll
    for (int o = 16; o; o >>= 1) lsum += __shfl_down_sync(0xffffffffu, lsum, o);
    if ((tid & 31) == 0) red[tid >> 5] = lsum;
    __syncthreads();
    if (tid == 0) {
        double t = 0.0;
#pragma unroll
        for (int w = 0; w < 8; w++) t += red[w];
        atomicAdd(&g_loss, t);
        __threadfence();
        unsigned done = atomicAdd(&g_done, 1u);
        if (done == (unsigned)(gridDim.x - 1)) {
            if (write_extras)
                out[LOSS_OFF] = (float)(0.25 * g_loss / (double)N_ELEMS);
            g_loss = 0.0;
            g_done = 0u;
        }
    }
}

extern "C" void kernel_launch(void* const* d_in, const int* in_sizes, int n_in,
                              void* d_out, int out_size) {
    const float* in  = (const float*)d_in[0];
    const float* emb = (const float*)d_in[1];
    if (n_in >= 2 && in_sizes[0] == K * D && in_sizes[1] == N_ELEMS) {
        const float* t = in; in = emb; emb = t;
    }
    float* out = (float*)d_out;

    cudaFuncSetAttribute(k_main, cudaFuncAttributeMaxDynamicSharedMemorySize, SMEM_BYTES);

    const int extras = (out_size > N_ELEMS) ? 1 : 0;

    k_main<<<NCTA, THREADS, SMEM_BYTES>>>(in, emb, out, extras);
}